// round 8
// baseline (speedup 1.0000x reference)
#include <cuda_runtime.h>
#include <cuda_bf16.h>
#include <stdint.h>

// ---------------------------------------------------------------------------
// Linear attention (causal QK^T, NO softmax) via chunked prefix-state, with
// projections folded into precomputed G = Wq^T Wk / sqrt(H), W2 = Wo Wv:
//   scores = Tn G Tn^T ; Z = tril(scores) @ Tn + (Tn G) @ Tpre ; proj = Z W2^T
// where T_c = Tn_c^T Tn_c and Tpre = exclusive prefix sum of T over chunks.
// ONE kernel launch total: persistent grid 256 (2 CTAs/SM co-resident),
// software grid barriers; CTA0/CTA1 build G/W2 inline during phase A.
// ---------------------------------------------------------------------------

#define NB      4
#define NSEQ    8192
#define CH      128
#define NCB     (NSEQ / CH)        // 64
#define NCHUNK  (NB * NCB)         // 256
#define TILE    16384              // 128*128
#define RSQRT_H 0.08838834764831845f

// Scratch (device globals: allocation-free rule)
__device__ __nv_bfloat16 g_S [NCHUNK * TILE];   // per-chunk gram T_c
__device__ __nv_bfloat16 g_M [NCHUNK * TILE];   // exclusive prefix Tpre
__device__ __nv_bfloat16 g_G [TILE];            // Wq^T Wk / sqrt(H)
__device__ __nv_bfloat16 g_W2[TILE];            // Wo @ Wv

// grid barrier state (zero-init; gen monotonically grows across graph replays)
__device__ int g_cnt = 0;
__device__ int g_gen = 0;

__device__ __forceinline__ void grid_bar() {
    __syncthreads();
    if (threadIdx.x == 0) {
        __threadfence();
        int gen = *((volatile int*)&g_gen);
        if (atomicAdd(&g_cnt, 1) == NCHUNK - 1) {
            g_cnt = 0;
            __threadfence();
            atomicExch(&g_gen, gen + 1);
        } else {
            while (*((volatile int*)&g_gen) == gen) __nanosleep(32);
        }
        __threadfence();
    }
    __syncthreads();
}

// =========================== helpers =======================================
__device__ __forceinline__ uint32_t smem_u32(const void* p) {
    uint32_t a;
    asm("{ .reg .u64 t; cvta.to.shared.u64 t, %1; cvt.u32.u64 %0, t; }"
        : "=r"(a) : "l"(p));
    return a;
}

// Swizzled byte offset inside a 128x128 bf16 tile (256B rows); colg = 16B group
__device__ __forceinline__ uint32_t swz(int row, int colg) {
    return (uint32_t)(row * 256) + (uint32_t)(((colg ^ (row & 7)) << 4));
}

__device__ __forceinline__ uint32_t pack_bf16(float lo, float hi) {
    __nv_bfloat162 h;
    h.x = __float2bfloat16(lo);
    h.y = __float2bfloat16(hi);
    return *reinterpret_cast<uint32_t*>(&h);
}

__device__ __forceinline__ void ldm4(uint32_t addr, uint32_t r[4]) {
    asm volatile("ldmatrix.sync.aligned.m8n8.x4.shared.b16 {%0,%1,%2,%3}, [%4];"
                 : "=r"(r[0]), "=r"(r[1]), "=r"(r[2]), "=r"(r[3]) : "r"(addr));
}
__device__ __forceinline__ void ldm4t(uint32_t addr, uint32_t r[4]) {
    asm volatile("ldmatrix.sync.aligned.m8n8.x4.trans.shared.b16 {%0,%1,%2,%3}, [%4];"
                 : "=r"(r[0]), "=r"(r[1]), "=r"(r[2]), "=r"(r[3]) : "r"(addr));
}

__device__ __forceinline__ void mma16816(float* c, const uint32_t a[4],
                                         uint32_t b0, uint32_t b1) {
    asm volatile(
        "mma.sync.aligned.m16n8k16.row.col.f32.bf16.bf16.f32 "
        "{%0,%1,%2,%3},{%4,%5,%6,%7},{%8,%9},{%0,%1,%2,%3};"
        : "+f"(c[0]), "+f"(c[1]), "+f"(c[2]), "+f"(c[3])
        : "r"(a[0]), "r"(a[1]), "r"(a[2]), "r"(a[3]), "r"(b0), "r"(b1));
}

// cp.async 128x128 bf16 gmem tile -> swizzled smem tile
__device__ __forceinline__ void cp_tile(uint32_t dst, const __nv_bfloat16* __restrict__ src,
                                        int tid) {
#pragma unroll
    for (int i = 0; i < 8; i++) {
        int idx = tid + i * 256;
        int row = idx >> 4, g = idx & 15;
        asm volatile("cp.async.cg.shared.global [%0], [%1], 16;"
                     :: "r"(dst + swz(row, g)),
                        "l"((const void*)(((const uint4*)src) + idx)));
    }
}
#define CP_COMMIT() asm volatile("cp.async.commit_group;" ::: "memory")
#define CP_WAIT_ALL() asm volatile("cp.async.wait_all;" ::: "memory")
#define CP_WAIT_GROUP(n) asm volatile("cp.async.wait_group %0;" :: "n"(n) : "memory")

// fp32 row-major 128x128 gmem -> bf16 swizzled smem tile (256 threads)
__device__ __forceinline__ void load_w(char* dst, const float* __restrict__ W, int tid) {
#pragma unroll
    for (int i = 0; i < 8; i++) {
        int idx = tid + i * 256;
        int row = idx >> 4, g = idx & 15;
        const float4* p = (const float4*)(W + row * 128 + g * 8);
        float4 v0 = p[0], v1 = p[1];
        uint4 o;
        o.x = pack_bf16(v0.x, v0.y);  o.y = pack_bf16(v0.z, v0.w);
        o.z = pack_bf16(v1.x, v1.y);  o.w = pack_bf16(v1.z, v1.w);
        *(uint4*)(dst + swz(row, g)) = o;
    }
}

// ---------------------------------------------------------------------------
// 128x128x128: C[m][n] += A' * B'^T on swizzled bf16 smem tiles.
// ATR/BTR: operand is the smem tile transposed (ldmatrix.trans).
// 8 warps: warp w owns rows mo=(w&3)*32, cols no=(w>>2)*64. acc[2][8][4].
// ---------------------------------------------------------------------------
template <int ATR, int BTR>
__device__ __forceinline__ void mm(uint32_t sa, uint32_t sb,
                                   float acc[2][8][4], int lane, int mo, int no) {
#pragma unroll
    for (int kk = 0; kk < 8; kk++) {
        uint32_t a[2][4], b[4][4];
#pragma unroll
        for (int mt = 0; mt < 2; mt++) {
            if (!ATR) {
                ldm4(sa + swz(mo + mt * 16 + (lane & 15), kk * 2 + (lane >> 4)), a[mt]);
            } else {
                ldm4t(sa + swz(kk * 16 + ((lane >> 4) << 3) + (lane & 7),
                               ((mo + mt * 16) >> 3) + ((lane >> 3) & 1)), a[mt]);
            }
        }
#pragma unroll
        for (int nt2 = 0; nt2 < 4; nt2++) {
            if (!BTR) {
                ldm4(sb + swz(no + nt2 * 16 + ((lane >> 4) << 3) + (lane & 7),
                              kk * 2 + ((lane >> 3) & 1)), b[nt2]);
            } else {
                ldm4t(sb + swz(kk * 16 + ((lane >> 3) & 1) * 8 + (lane & 7),
                               ((no + nt2 * 16) >> 3) + (lane >> 4)), b[nt2]);
            }
        }
#pragma unroll
        for (int mt = 0; mt < 2; mt++)
#pragma unroll
            for (int nt = 0; nt < 8; nt++)
                mma16816(acc[mt][nt], a[mt],
                         b[nt >> 1][(nt & 1) * 2], b[nt >> 1][(nt & 1) * 2 + 1]);
    }
}

__device__ __forceinline__ void zacc(float acc[2][8][4]) {
#pragma unroll
    for (int mt = 0; mt < 2; mt++)
#pragma unroll
        for (int nt = 0; nt < 8; nt++)
#pragma unroll
            for (int j = 0; j < 4; j++) acc[mt][nt][j] = 0.0f;
}

// accum (scaled) -> bf16 row-major gmem tile
__device__ __forceinline__ void store_bf16(float acc[2][8][4],
                                           __nv_bfloat16* __restrict__ dst,
                                           int lane, int mo, int no, float scale) {
    int g = lane >> 2, t = lane & 3;
#pragma unroll
    for (int mt = 0; mt < 2; mt++)
#pragma unroll
        for (int nt = 0; nt < 8; nt++) {
            int col = no + nt * 8 + 2 * t;
            int r0 = mo + mt * 16 + g;
            *(uint32_t*)(dst + r0 * 128 + col) =
                pack_bf16(acc[mt][nt][0] * scale, acc[mt][nt][1] * scale);
            *(uint32_t*)(dst + (r0 + 8) * 128 + col) =
                pack_bf16(acc[mt][nt][2] * scale, acc[mt][nt][3] * scale);
        }
}

// accum -> bf16 swizzled smem tile
__device__ __forceinline__ void store_sw(float acc[2][8][4], char* buf,
                                         int lane, int mo, int no) {
    int g = lane >> 2, t = lane & 3;
#pragma unroll
    for (int mt = 0; mt < 2; mt++)
#pragma unroll
        for (int nt = 0; nt < 8; nt++) {
            int col = no + nt * 8 + 2 * t;
            int r0 = mo + mt * 16 + g, r1 = r0 + 8;
            *(uint32_t*)(buf + swz(r0, col >> 3) + (col & 7) * 2) =
                pack_bf16(acc[mt][nt][0], acc[mt][nt][1]);
            *(uint32_t*)(buf + swz(r1, col >> 3) + (col & 7) * 2) =
                pack_bf16(acc[mt][nt][2], acc[mt][nt][3]);
        }
}

// per-thread bf16 stash of accumulator to plain row-major smem (own slots only)
__device__ __forceinline__ void stash_store(float acc[2][8][4], char* buf,
                                            int lane, int mo, int no) {
    int g = lane >> 2, t = lane & 3;
#pragma unroll
    for (int mt = 0; mt < 2; mt++)
#pragma unroll
        for (int nt = 0; nt < 8; nt++) {
            int col = no + nt * 8 + 2 * t;
            int r0 = mo + mt * 16 + g, r1 = r0 + 8;
            *(uint32_t*)(buf + (r0 * 128 + col) * 2) = pack_bf16(acc[mt][nt][0], acc[mt][nt][1]);
            *(uint32_t*)(buf + (r1 * 128 + col) * 2) = pack_bf16(acc[mt][nt][2], acc[mt][nt][3]);
        }
}
__device__ __forceinline__ void stash_add(float acc[2][8][4], const char* buf,
                                          int lane, int mo, int no) {
    int g = lane >> 2, t = lane & 3;
#pragma unroll
    for (int mt = 0; mt < 2; mt++)
#pragma unroll
        for (int nt = 0; nt < 8; nt++) {
            int col = no + nt * 8 + 2 * t;
            int r0 = mo + mt * 16 + g, r1 = r0 + 8;
            uint32_t w0 = *(const uint32_t*)(buf + (r0 * 128 + col) * 2);
            uint32_t w1 = *(const uint32_t*)(buf + (r1 * 128 + col) * 2);
            __nv_bfloat162 h0 = *reinterpret_cast<__nv_bfloat162*>(&w0);
            __nv_bfloat162 h1 = *reinterpret_cast<__nv_bfloat162*>(&w1);
            acc[mt][nt][0] += __bfloat162float(h0.x);
            acc[mt][nt][1] += __bfloat162float(h0.y);
            acc[mt][nt][2] += __bfloat162float(h1.x);
            acc[mt][nt][3] += __bfloat162float(h1.y);
        }
}

// ===========================================================================
// Fused persistent kernel. smem: b0 / b1 / b2 (3 x 32KB).
//  b0 = Tn (resident A->C) -> proj stage
//  b1 = (CTA0/1: weight) -> G -> U -> P -> Z
//  b2 = (CTA0/1: weight) -> Tpre -> Z2 stash -> W2
// ===========================================================================
#define KF_SMEM (3 * 32768)

extern "C" __global__ void __launch_bounds__(256, 2)
k_fused(const float* __restrict__ tokens,
        const float* __restrict__ Wq, const float* __restrict__ Wk,
        const float* __restrict__ Wv, const float* __restrict__ Wo,
        const float* __restrict__ g1, const float* __restrict__ b1v,
        const float* __restrict__ g2, const float* __restrict__ b2v,
        float* __restrict__ out) {
    extern __shared__ char smem[];
    char* b0 = smem;
    char* b1 = smem + 32768;
    char* b2 = smem + 65536;
    int tid = threadIdx.x, wid = tid >> 5, lane = tid & 31;
    int mo = (wid & 3) * 32, no = (wid >> 2) * 64;
    int g = lane >> 2, t = lane & 3;
    int cid = blockIdx.x, base = cid * CH;
    uint32_t sb0 = smem_u32(b0), sb1 = smem_u32(b1), sb2 = smem_u32(b2);

    float acc[2][8][4];

    // ============================ PHASE A ==================================
    // LN1 -> b0 (swizzled bf16), resident through phase C
    for (int r = wid; r < CH; r += 8) {
        float4 v = ((const float4*)(tokens + (size_t)(base + r) * 128))[lane];
        float s  = v.x + v.y + v.z + v.w;
        float s2 = v.x * v.x + v.y * v.y + v.z * v.z + v.w * v.w;
#pragma unroll
        for (int o = 16; o; o >>= 1) {
            s  += __shfl_xor_sync(0xffffffffu, s, o);
            s2 += __shfl_xor_sync(0xffffffffu, s2, o);
        }
        float mu  = s * (1.0f / 128.0f);
        float var = fmaxf(s2 * (1.0f / 128.0f) - mu * mu, 0.0f);
        float inv = rsqrtf(var + 1e-5f);
        float4 gg = ((const float4*)g1)[lane];
        float4 bb = ((const float4*)b1v)[lane];
        float o0 = (v.x - mu) * inv * gg.x + bb.x;
        float o1 = (v.y - mu) * inv * gg.y + bb.y;
        float o2 = (v.z - mu) * inv * gg.z + bb.z;
        float o3 = (v.w - mu) * inv * gg.w + bb.w;
        uint32_t off = swz(r, lane >> 1) + (lane & 1) * 8;
        *(uint32_t*)(b0 + off)     = pack_bf16(o0, o1);
        *(uint32_t*)(b0 + off + 4) = pack_bf16(o2, o3);
    }
    __syncthreads();

    // T = Tn^T @ Tn -> g_S
    zacc(acc);
    mm<1, 1>(sb0, sb0, acc, lane, mo, no);
    store_bf16(acc, g_S + (size_t)cid * TILE, lane, mo, no, 1.0f);

    // CTA 0 builds G = Wq^T Wk / sqrt(H); CTA 1 builds W2 = Wo @ Wv.
    // b1/b2 are idle in phase A for every CTA; published by grid_bar below.
    if (cid < 2) {
        load_w(b1, cid == 0 ? Wq : Wo, tid);
        load_w(b2, cid == 0 ? Wk : Wv, tid);
        __syncthreads();
        zacc(acc);
        if (cid == 0) {
            mm<1, 1>(sb1, sb2, acc, lane, mo, no);   // G[t1][t2] = sum_h Wq[h][t1] Wk[h][t2]
            store_bf16(acc, g_G, lane, mo, no, RSQRT_H);
        } else {
            mm<0, 1>(sb1, sb2, acc, lane, mo, no);   // W2[o][t] = sum_v Wo[o][v] Wv[v][t]
            store_bf16(acc, g_W2, lane, mo, no, 1.0f);
        }
    }

    grid_bar();                             // all T (+ G, W2) visible

    // ============================ PHASE B ==================================
    cp_tile(sb1, g_G, tid);                 // prefetch G (group age 1 later)
    CP_COMMIT();

    {
        int tg = cid * 256 + tid;           // 65536 threads == elements
        int b = tg >> 14, e = tg & 16383;
        const __nv_bfloat16* S = g_S + (size_t)b * NCB * TILE + e;
        __nv_bfloat16* M = g_M + (size_t)b * NCB * TILE + e;
        float s = 0.0f;
#pragma unroll 8
        for (int c = 0; c < NCB; c++) {
            M[(size_t)c * TILE] = __float2bfloat16(s);
            s += __bfloat162float(S[(size_t)c * TILE]);
        }
    }

    grid_bar();                             // all Tpre visible

    // ============================ PHASE C ==================================
    // Tpre -> b2 (own group); wait only for G, then U = Tn @ G under Tpre load
    cp_tile(sb2, g_M + (size_t)cid * TILE, tid);
    CP_COMMIT();
    CP_WAIT_GROUP(1);                       // G landed
    __syncthreads();
    zacc(acc);
    mm<0, 1>(sb0, sb1, acc, lane, mo, no);  // U[i][t] = sum Tn[i][t1] G[t1][t]
    CP_WAIT_GROUP(0);                       // Tpre landed
    __syncthreads();                        // G dead everywhere

    store_sw(acc, b1, lane, mo, no);        // U -> b1
    __syncthreads();

    // Z2 = U @ Tpre
    zacc(acc);
    mm<0, 1>(sb1, sb2, acc, lane, mo, no);
    __syncthreads();                        // Tpre dead
    stash_store(acc, b2, lane, mo, no);     // Z2 stash -> b2 (own slots)

    // scores = U @ Tn^T
    zacc(acc);
    mm<0, 0>(sb1, sb0, acc, lane, mo, no);
    __syncthreads();                        // U dead

    // masked P -> b1
#pragma unroll
    for (int mt = 0; mt < 2; mt++)
#pragma unroll
        for (int nt = 0; nt < 8; nt++) {
            int col = no + nt * 8 + 2 * t;
            int r0 = mo + mt * 16 + g, r1 = r0 + 8;
            float v0 = (col     <= r0) ? acc[mt][nt][0] : 0.0f;
            float v1 = (col + 1 <= r0) ? acc[mt][nt][1] : 0.0f;
            float v2 = (col     <= r1) ? acc[mt][nt][2] : 0.0f;
            float v3 = (col + 1 <= r1) ? acc[mt][nt][3] : 0.0f;
            *(uint32_t*)(b1 + swz(r0, col >> 3) + (col & 7) * 2) = pack_bf16(v0, v1);
            *(uint32_t*)(b1 + swz(r1, col >> 3) + (col & 7) * 2) = pack_bf16(v2, v3);
        }
    __syncthreads();                        // P visible

    // Z = P @ Tn + Z2(stash)
    zacc(acc);
    mm<0, 1>(sb1, sb0, acc, lane, mo, no);
    stash_add(acc, b2, lane, mo, no);
    __syncthreads();                        // P dead, stash consumed

    // Z -> b1 ; W2 -> b2
    store_sw(acc, b1, lane, mo, no);
    cp_tile(sb2, g_W2, tid);
    CP_COMMIT(); CP_WAIT_ALL();
    __syncthreads();

    // proj = Z @ W2^T
    zacc(acc);
    mm<0, 0>(sb1, sb2, acc, lane, mo, no);
    __syncthreads();                        // Tn (b0) dead

    // 0.1*proj -> b0 bf16 row-major
#pragma unroll
    for (int mt = 0; mt < 2; mt++)
#pragma unroll
        for (int nt = 0; nt < 8; nt++) {
            int col = no + nt * 8 + 2 * t;
            int r0 = mo + mt * 16 + g, r1 = r0 + 8;
            *(uint32_t*)(b0 + (r0 * 128 + col) * 2) =
                pack_bf16(0.1f * acc[mt][nt][0], 0.1f * acc[mt][nt][1]);
            *(uint32_t*)(b0 + (r1 * 128 + col) * 2) =
                pack_bf16(0.1f * acc[mt][nt][2], 0.1f * acc[mt][nt][3]);
        }
    __syncthreads();

    // LN2(tokens + res) -> out
    for (int r = wid; r < CH; r += 8) {
        float4 tv = ((const float4*)(tokens + (size_t)(base + r) * 128))[lane];
        uint2 pr = *(const uint2*)(b0 + (r * 128 + lane * 4) * 2);
        __nv_bfloat162 p0 = *reinterpret_cast<__nv_bfloat162*>(&pr.x);
        __nv_bfloat162 p1 = *reinterpret_cast<__nv_bfloat162*>(&pr.y);
        float x0 = tv.x + __bfloat162float(p0.x);
        float x1 = tv.y + __bfloat162float(p0.y);
        float x2 = tv.z + __bfloat162float(p1.x);
        float x3 = tv.w + __bfloat162float(p1.y);
        float s  = x0 + x1 + x2 + x3;
        float s2 = x0 * x0 + x1 * x1 + x2 * x2 + x3 * x3;
#pragma unroll
        for (int o = 16; o; o >>= 1) {
            s  += __shfl_xor_sync(0xffffffffu, s, o);
            s2 += __shfl_xor_sync(0xffffffffu, s2, o);
        }
        float mu  = s * (1.0f / 128.0f);
        float var = fmaxf(s2 * (1.0f / 128.0f) - mu * mu, 0.0f);
        float inv = rsqrtf(var + 1e-5f);
        float4 gg = ((const float4*)g2)[lane];
        float4 bb = ((const float4*)b2v)[lane];
        float4 o4;
        o4.x = (x0 - mu) * inv * gg.x + bb.x;
        o4.y = (x1 - mu) * inv * gg.y + bb.y;
        o4.z = (x2 - mu) * inv * gg.z + bb.z;
        o4.w = (x3 - mu) * inv * gg.w + bb.w;
        ((float4*)(out + (size_t)(base + r) * 128))[lane] = o4;
    }
}

// ===========================================================================
extern "C" void kernel_launch(void* const* d_in, const int* in_sizes, int n_in,
                              void* d_out, int out_size) {
    const float* tokens = (const float*)d_in[0];
    const float* Wq = (const float*)d_in[1];
    const float* Wk = (const float*)d_in[2];
    const float* Wv = (const float*)d_in[3];
    const float* Wo = (const float*)d_in[4];
    const float* g1 = (const float*)d_in[5];
    const float* b1 = (const float*)d_in[6];
    const float* g2 = (const float*)d_in[7];
    const float* b2 = (const float*)d_in[8];
    float* out = (float*)d_out;

    cudaFuncSetAttribute(k_fused, cudaFuncAttributeMaxDynamicSharedMemorySize, KF_SMEM);

    k_fused<<<NCHUNK, 256, KF_SMEM>>>(tokens, Wq, Wk, Wv, Wo, g1, b1, g2, b2, out);
}

// round 9
// speedup vs baseline: 1.4646x; 1.4646x over previous
#include <cuda_runtime.h>
#include <cuda_bf16.h>
#include <stdint.h>

// ---------------------------------------------------------------------------
// Linear attention (causal QK^T, NO softmax) via chunked prefix-state, with
// the projections folded into precomputed G = Wq^T Wk / sqrt(H), W2 = Wo Wv:
//   scores = Tn G Tn^T ; Z = tril(scores) @ Tn + (Tn G) @ Tpre ; proj = Z W2^T
// where T_c = Tn_c^T Tn_c and Tpre = exclusive prefix sum of T over chunks.
// Launch 1: k_prep (grid=2) builds G and W2 straight from fp32 weights.
// Launch 2: persistent k_fused (grid 256 co-resident at 2 CTAs/SM) with
// software grid barriers.  (R8 showed inline prep in the persistent kernel
// regresses badly -- keep prep separate.)
// ---------------------------------------------------------------------------

#define NB      4
#define NSEQ    8192
#define CH      128
#define NCB     (NSEQ / CH)        // 64
#define NCHUNK  (NB * NCB)         // 256
#define TILE    16384              // 128*128
#define RSQRT_H 0.08838834764831845f

// Scratch (device globals: allocation-free rule)
__device__ __nv_bfloat16 g_S [NCHUNK * TILE];   // per-chunk gram T_c
__device__ __nv_bfloat16 g_M [NCHUNK * TILE];   // exclusive prefix Tpre
__device__ __nv_bfloat16 g_G [TILE];            // Wq^T Wk / sqrt(H)
__device__ __nv_bfloat16 g_W2[TILE];            // Wo @ Wv

// grid barrier state (zero-init; gen monotonically grows across graph replays)
__device__ int g_cnt = 0;
__device__ int g_gen = 0;

__device__ __forceinline__ void grid_bar() {
    __syncthreads();
    if (threadIdx.x == 0) {
        __threadfence();
        int gen = *((volatile int*)&g_gen);
        if (atomicAdd(&g_cnt, 1) == NCHUNK - 1) {
            g_cnt = 0;
            __threadfence();
            atomicExch(&g_gen, gen + 1);
        } else {
            while (*((volatile int*)&g_gen) == gen) __nanosleep(32);
        }
        __threadfence();
    }
    __syncthreads();
}

// =========================== helpers =======================================
__device__ __forceinline__ uint32_t smem_u32(const void* p) {
    uint32_t a;
    asm("{ .reg .u64 t; cvta.to.shared.u64 t, %1; cvt.u32.u64 %0, t; }"
        : "=r"(a) : "l"(p));
    return a;
}

// Swizzled byte offset inside a 128x128 bf16 tile (256B rows); colg = 16B group
__device__ __forceinline__ uint32_t swz(int row, int colg) {
    return (uint32_t)(row * 256) + (uint32_t)(((colg ^ (row & 7)) << 4));
}

__device__ __forceinline__ uint32_t pack_bf16(float lo, float hi) {
    __nv_bfloat162 h;
    h.x = __float2bfloat16(lo);
    h.y = __float2bfloat16(hi);
    return *reinterpret_cast<uint32_t*>(&h);
}

__device__ __forceinline__ void ldm4(uint32_t addr, uint32_t r[4]) {
    asm volatile("ldmatrix.sync.aligned.m8n8.x4.shared.b16 {%0,%1,%2,%3}, [%4];"
                 : "=r"(r[0]), "=r"(r[1]), "=r"(r[2]), "=r"(r[3]) : "r"(addr));
}
__device__ __forceinline__ void ldm4t(uint32_t addr, uint32_t r[4]) {
    asm volatile("ldmatrix.sync.aligned.m8n8.x4.trans.shared.b16 {%0,%1,%2,%3}, [%4];"
                 : "=r"(r[0]), "=r"(r[1]), "=r"(r[2]), "=r"(r[3]) : "r"(addr));
}

__device__ __forceinline__ void mma16816(float* c, const uint32_t a[4],
                                         uint32_t b0, uint32_t b1) {
    asm volatile(
        "mma.sync.aligned.m16n8k16.row.col.f32.bf16.bf16.f32 "
        "{%0,%1,%2,%3},{%4,%5,%6,%7},{%8,%9},{%0,%1,%2,%3};"
        : "+f"(c[0]), "+f"(c[1]), "+f"(c[2]), "+f"(c[3])
        : "r"(a[0]), "r"(a[1]), "r"(a[2]), "r"(a[3]), "r"(b0), "r"(b1));
}

// cp.async 128x128 bf16 gmem tile -> swizzled smem tile
__device__ __forceinline__ void cp_tile(uint32_t dst, const __nv_bfloat16* __restrict__ src,
                                        int tid) {
#pragma unroll
    for (int i = 0; i < 8; i++) {
        int idx = tid + i * 256;
        int row = idx >> 4, g = idx & 15;
        asm volatile("cp.async.cg.shared.global [%0], [%1], 16;"
                     :: "r"(dst + swz(row, g)),
                        "l"((const void*)(((const uint4*)src) + idx)));
    }
}
#define CP_COMMIT() asm volatile("cp.async.commit_group;" ::: "memory")
#define CP_WAIT()   asm volatile("cp.async.wait_all;" ::: "memory")

// fp32 row-major 128x128 gmem -> bf16 swizzled smem tile (256 threads)
__device__ __forceinline__ void load_w(char* dst, const float* __restrict__ W, int tid) {
#pragma unroll
    for (int i = 0; i < 8; i++) {
        int idx = tid + i * 256;
        int row = idx >> 4, g = idx & 15;
        const float4* p = (const float4*)(W + row * 128 + g * 8);
        float4 v0 = p[0], v1 = p[1];
        uint4 o;
        o.x = pack_bf16(v0.x, v0.y);  o.y = pack_bf16(v0.z, v0.w);
        o.z = pack_bf16(v1.x, v1.y);  o.w = pack_bf16(v1.z, v1.w);
        *(uint4*)(dst + swz(row, g)) = o;
    }
}

// ---------------------------------------------------------------------------
// 128x128x128: C[m][n] += A' * B'^T on swizzled bf16 smem tiles.
// ATR/BTR: operand is the smem tile transposed (ldmatrix.trans).
// 8 warps: warp w owns rows mo=(w&3)*32, cols no=(w>>2)*64. acc[2][8][4].
// ---------------------------------------------------------------------------
template <int ATR, int BTR>
__device__ __forceinline__ void mm(uint32_t sa, uint32_t sb,
                                   float acc[2][8][4], int lane, int mo, int no) {
#pragma unroll
    for (int kk = 0; kk < 8; kk++) {
        uint32_t a[2][4], b[4][4];
#pragma unroll
        for (int mt = 0; mt < 2; mt++) {
            if (!ATR) {
                ldm4(sa + swz(mo + mt * 16 + (lane & 15), kk * 2 + (lane >> 4)), a[mt]);
            } else {
                ldm4t(sa + swz(kk * 16 + ((lane >> 4) << 3) + (lane & 7),
                               ((mo + mt * 16) >> 3) + ((lane >> 3) & 1)), a[mt]);
            }
        }
#pragma unroll
        for (int nt2 = 0; nt2 < 4; nt2++) {
            if (!BTR) {
                ldm4(sb + swz(no + nt2 * 16 + ((lane >> 4) << 3) + (lane & 7),
                              kk * 2 + ((lane >> 3) & 1)), b[nt2]);
            } else {
                ldm4t(sb + swz(kk * 16 + ((lane >> 3) & 1) * 8 + (lane & 7),
                               ((no + nt2 * 16) >> 3) + (lane >> 4)), b[nt2]);
            }
        }
#pragma unroll
        for (int mt = 0; mt < 2; mt++)
#pragma unroll
            for (int nt = 0; nt < 8; nt++)
                mma16816(acc[mt][nt], a[mt],
                         b[nt >> 1][(nt & 1) * 2], b[nt >> 1][(nt & 1) * 2 + 1]);
    }
}

__device__ __forceinline__ void zacc(float acc[2][8][4]) {
#pragma unroll
    for (int mt = 0; mt < 2; mt++)
#pragma unroll
        for (int nt = 0; nt < 8; nt++)
#pragma unroll
            for (int j = 0; j < 4; j++) acc[mt][nt][j] = 0.0f;
}

// accum (scaled) -> bf16 row-major gmem tile
__device__ __forceinline__ void store_bf16(float acc[2][8][4],
                                           __nv_bfloat16* __restrict__ dst,
                                           int lane, int mo, int no, float scale) {
    int g = lane >> 2, t = lane & 3;
#pragma unroll
    for (int mt = 0; mt < 2; mt++)
#pragma unroll
        for (int nt = 0; nt < 8; nt++) {
            int col = no + nt * 8 + 2 * t;
            int r0 = mo + mt * 16 + g;
            *(uint32_t*)(dst + r0 * 128 + col) =
                pack_bf16(acc[mt][nt][0] * scale, acc[mt][nt][1] * scale);
            *(uint32_t*)(dst + (r0 + 8) * 128 + col) =
                pack_bf16(acc[mt][nt][2] * scale, acc[mt][nt][3] * scale);
        }
}

// accum -> bf16 swizzled smem tile
__device__ __forceinline__ void store_sw(float acc[2][8][4], char* buf,
                                         int lane, int mo, int no) {
    int g = lane >> 2, t = lane & 3;
#pragma unroll
    for (int mt = 0; mt < 2; mt++)
#pragma unroll
        for (int nt = 0; nt < 8; nt++) {
            int col = no + nt * 8 + 2 * t;
            int r0 = mo + mt * 16 + g, r1 = r0 + 8;
            *(uint32_t*)(buf + swz(r0, col >> 3) + (col & 7) * 2) =
                pack_bf16(acc[mt][nt][0], acc[mt][nt][1]);
            *(uint32_t*)(buf + swz(r1, col >> 3) + (col & 7) * 2) =
                pack_bf16(acc[mt][nt][2], acc[mt][nt][3]);
        }
}

// per-thread bf16 stash of accumulator to plain row-major smem (own slots only)
__device__ __forceinline__ void stash_store(float acc[2][8][4], char* buf,
                                            int lane, int mo, int no) {
    int g = lane >> 2, t = lane & 3;
#pragma unroll
    for (int mt = 0; mt < 2; mt++)
#pragma unroll
        for (int nt = 0; nt < 8; nt++) {
            int col = no + nt * 8 + 2 * t;
            int r0 = mo + mt * 16 + g, r1 = r0 + 8;
            *(uint32_t*)(buf + (r0 * 128 + col) * 2) = pack_bf16(acc[mt][nt][0], acc[mt][nt][1]);
            *(uint32_t*)(buf + (r1 * 128 + col) * 2) = pack_bf16(acc[mt][nt][2], acc[mt][nt][3]);
        }
}
__device__ __forceinline__ void stash_add(float acc[2][8][4], const char* buf,
                                          int lane, int mo, int no) {
    int g = lane >> 2, t = lane & 3;
#pragma unroll
    for (int mt = 0; mt < 2; mt++)
#pragma unroll
        for (int nt = 0; nt < 8; nt++) {
            int col = no + nt * 8 + 2 * t;
            int r0 = mo + mt * 16 + g, r1 = r0 + 8;
            uint32_t w0 = *(const uint32_t*)(buf + (r0 * 128 + col) * 2);
            uint32_t w1 = *(const uint32_t*)(buf + (r1 * 128 + col) * 2);
            __nv_bfloat162 h0 = *reinterpret_cast<__nv_bfloat162*>(&w0);
            __nv_bfloat162 h1 = *reinterpret_cast<__nv_bfloat162*>(&w1);
            acc[mt][nt][0] += __bfloat162float(h0.x);
            acc[mt][nt][1] += __bfloat162float(h0.y);
            acc[mt][nt][2] += __bfloat162float(h1.x);
            acc[mt][nt][3] += __bfloat162float(h1.y);
        }
}

// ===========================================================================
// Kernel 0: ONE prep launch (grid=2).  Reads fp32 weights directly.
//   CTA 0: G  = Wq^T Wk / sqrt(H)     CTA 1: W2 = Wo @ Wv
// ===========================================================================
#define KP_SMEM (2 * 32768)

extern "C" __global__ void __launch_bounds__(256, 1)
k_prep(const float* __restrict__ Wq, const float* __restrict__ Wk,
       const float* __restrict__ Wv, const float* __restrict__ Wo) {
    extern __shared__ char smem[];
    char* a = smem;
    char* b = smem + 32768;
    int tid = threadIdx.x, wid = tid >> 5, lane = tid & 31;
    int mo = (wid & 3) * 32, no = (wid >> 2) * 64;
    uint32_t sa = smem_u32(a), sb = smem_u32(b);
    float acc[2][8][4];

    if (blockIdx.x == 0) {
        load_w(a, Wq, tid);
        load_w(b, Wk, tid);
        __syncthreads();
        zacc(acc);
        mm<1, 1>(sa, sb, acc, lane, mo, no);   // G[t1][t2] = sum_h Wq[h][t1] Wk[h][t2]
        store_bf16(acc, g_G, lane, mo, no, RSQRT_H);
    } else {
        load_w(a, Wo, tid);
        load_w(b, Wv, tid);
        __syncthreads();
        zacc(acc);
        mm<0, 1>(sa, sb, acc, lane, mo, no);   // W2[o][t] = sum_v Wo[o][v] Wv[v][t]
        store_bf16(acc, g_W2, lane, mo, no, 1.0f);
    }
}

// ===========================================================================
// Fused persistent kernel (R7 version).  smem: b0 / b1 / b2 (3 x 32KB).
//  b0 = Tn (resident A->C) -> proj stage
//  b1 = G -> U -> P -> Z
//  b2 = Tpre -> Z2 stash -> W2
// ===========================================================================
#define KF_SMEM (3 * 32768)

extern "C" __global__ void __launch_bounds__(256, 2)
k_fused(const float* __restrict__ tokens,
        const float* __restrict__ g1, const float* __restrict__ b1v,
        const float* __restrict__ g2, const float* __restrict__ b2v,
        float* __restrict__ out) {
    extern __shared__ char smem[];
    char* b0 = smem;
    char* b1 = smem + 32768;
    char* b2 = smem + 65536;
    int tid = threadIdx.x, wid = tid >> 5, lane = tid & 31;
    int mo = (wid & 3) * 32, no = (wid >> 2) * 64;
    int g = lane >> 2, t = lane & 3;
    int cid = blockIdx.x, base = cid * CH;
    uint32_t sb0 = smem_u32(b0), sb1 = smem_u32(b1), sb2 = smem_u32(b2);

    float acc[2][8][4];

    // ============================ PHASE A ==================================
    cp_tile(sb1, g_G, tid);                 // G prefetch (ready by phase C)
    CP_COMMIT();

    for (int r = wid; r < CH; r += 8) {
        float4 v = ((const float4*)(tokens + (size_t)(base + r) * 128))[lane];
        float s  = v.x + v.y + v.z + v.w;
        float s2 = v.x * v.x + v.y * v.y + v.z * v.z + v.w * v.w;
#pragma unroll
        for (int o = 16; o; o >>= 1) {
            s  += __shfl_xor_sync(0xffffffffu, s, o);
            s2 += __shfl_xor_sync(0xffffffffu, s2, o);
        }
        float mu  = s * (1.0f / 128.0f);
        float var = fmaxf(s2 * (1.0f / 128.0f) - mu * mu, 0.0f);
        float inv = rsqrtf(var + 1e-5f);
        float4 gg = ((const float4*)g1)[lane];
        float4 bb = ((const float4*)b1v)[lane];
        float o0 = (v.x - mu) * inv * gg.x + bb.x;
        float o1 = (v.y - mu) * inv * gg.y + bb.y;
        float o2 = (v.z - mu) * inv * gg.z + bb.z;
        float o3 = (v.w - mu) * inv * gg.w + bb.w;
        uint32_t off = swz(r, lane >> 1) + (lane & 1) * 8;
        *(uint32_t*)(b0 + off)     = pack_bf16(o0, o1);
        *(uint32_t*)(b0 + off + 4) = pack_bf16(o2, o3);
    }
    CP_WAIT();
    __syncthreads();

    // T = Tn^T @ Tn -> g_S
    zacc(acc);
    mm<1, 1>(sb0, sb0, acc, lane, mo, no);
    store_bf16(acc, g_S + (size_t)cid * TILE, lane, mo, no, 1.0f);

    grid_bar();                             // all T visible

    // ============================ PHASE B ==================================
    {
        int tg = cid * 256 + tid;           // 65536 threads == elements
        int b = tg >> 14, e = tg & 16383;
        const __nv_bfloat16* S = g_S + (size_t)b * NCB * TILE + e;
        __nv_bfloat16* M = g_M + (size_t)b * NCB * TILE + e;
        float s = 0.0f;
#pragma unroll 8
        for (int c = 0; c < NCB; c++) {
            M[(size_t)c * TILE] = __float2bfloat16(s);
            s += __bfloat162float(S[(size_t)c * TILE]);
        }
    }

    grid_bar();                             // all Tpre visible

    // ============================ PHASE C ==================================
    // Tpre -> b2 overlapped with U = Tn @ G
    cp_tile(sb2, g_M + (size_t)cid * TILE, tid);
    CP_COMMIT();
    zacc(acc);
    mm<0, 1>(sb0, sb1, acc, lane, mo, no);  // U[i][t] = sum Tn[i][t1] G[t1][t]
    CP_WAIT();
    __syncthreads();                        // G dead, Tpre ready

    store_sw(acc, b1, lane, mo, no);        // U -> b1
    __syncthreads();

    // Z2 = U @ Tpre
    zacc(acc);
    mm<0, 1>(sb1, sb2, acc, lane, mo, no);
    __syncthreads();                        // Tpre dead
    stash_store(acc, b2, lane, mo, no);     // Z2 stash -> b2 (own slots)

    // scores = U @ Tn^T
    zacc(acc);
    mm<0, 0>(sb1, sb0, acc, lane, mo, no);
    __syncthreads();                        // U dead

    // masked P -> b1
#pragma unroll
    for (int mt = 0; mt < 2; mt++)
#pragma unroll
        for (int nt = 0; nt < 8; nt++) {
            int col = no + nt * 8 + 2 * t;
            int r0 = mo + mt * 16 + g, r1 = r0 + 8;
            float v0 = (col     <= r0) ? acc[mt][nt][0] : 0.0f;
            float v1 = (col + 1 <= r0) ? acc[mt][nt][1] : 0.0f;
            float v2 = (col     <= r1) ? acc[mt][nt][2] : 0.0f;
            float v3 = (col + 1 <= r1) ? acc[mt][nt][3] : 0.0f;
            *(uint32_t*)(b1 + swz(r0, col >> 3) + (col & 7) * 2) = pack_bf16(v0, v1);
            *(uint32_t*)(b1 + swz(r1, col >> 3) + (col & 7) * 2) = pack_bf16(v2, v3);
        }
    __syncthreads();                        // P visible

    // Z = P @ Tn + Z2(stash)
    zacc(acc);
    mm<0, 1>(sb1, sb0, acc, lane, mo, no);
    stash_add(acc, b2, lane, mo, no);
    __syncthreads();                        // P dead, stash consumed

    // Z -> b1 ; W2 -> b2
    store_sw(acc, b1, lane, mo, no);
    cp_tile(sb2, g_W2, tid);
    CP_COMMIT(); CP_WAIT();
    __syncthreads();

    // proj = Z @ W2^T
    zacc(acc);
    mm<0, 0>(sb1, sb2, acc, lane, mo, no);
    __syncthreads();                        // Tn (b0) dead

    // 0.1*proj -> b0 bf16 row-major
#pragma unroll
    for (int mt = 0; mt < 2; mt++)
#pragma unroll
        for (int nt = 0; nt < 8; nt++) {
            int col = no + nt * 8 + 2 * t;
            int r0 = mo + mt * 16 + g, r1 = r0 + 8;
            *(uint32_t*)(b0 + (r0 * 128 + col) * 2) =
                pack_bf16(0.1f * acc[mt][nt][0], 0.1f * acc[mt][nt][1]);
            *(uint32_t*)(b0 + (r1 * 128 + col) * 2) =
                pack_bf16(0.1f * acc[mt][nt][2], 0.1f * acc[mt][nt][3]);
        }
    __syncthreads();

    // LN2(tokens + res) -> out
    for (int r = wid; r < CH; r += 8) {
        float4 tv = ((const float4*)(tokens + (size_t)(base + r) * 128))[lane];
        uint2 pr = *(const uint2*)(b0 + (r * 128 + lane * 4) * 2);
        __nv_bfloat162 p0 = *reinterpret_cast<__nv_bfloat162*>(&pr.x);
        __nv_bfloat162 p1 = *reinterpret_cast<__nv_bfloat162*>(&pr.y);
        float x0 = tv.x + __bfloat162float(p0.x);
        float x1 = tv.y + __bfloat162float(p0.y);
        float x2 = tv.z + __bfloat162float(p1.x);
        float x3 = tv.w + __bfloat162float(p1.y);
        float s  = x0 + x1 + x2 + x3;
        float s2 = x0 * x0 + x1 * x1 + x2 * x2 + x3 * x3;
#pragma unroll
        for (int o = 16; o; o >>= 1) {
            s  += __shfl_xor_sync(0xffffffffu, s, o);
            s2 += __shfl_xor_sync(0xffffffffu, s2, o);
        }
        float mu  = s * (1.0f / 128.0f);
        float var = fmaxf(s2 * (1.0f / 128.0f) - mu * mu, 0.0f);
        float inv = rsqrtf(var + 1e-5f);
        float4 gg = ((const float4*)g2)[lane];
        float4 bb = ((const float4*)b2v)[lane];
        float4 o4;
        o4.x = (x0 - mu) * inv * gg.x + bb.x;
        o4.y = (x1 - mu) * inv * gg.y + bb.y;
        o4.z = (x2 - mu) * inv * gg.z + bb.z;
        o4.w = (x3 - mu) * inv * gg.w + bb.w;
        ((float4*)(out + (size_t)(base + r) * 128))[lane] = o4;
    }
}

// ===========================================================================
extern "C" void kernel_launch(void* const* d_in, const int* in_sizes, int n_in,
                              void* d_out, int out_size) {
    const float* tokens = (const float*)d_in[0];
    const float* Wq = (const float*)d_in[1];
    const float* Wk = (const float*)d_in[2];
    const float* Wv = (const float*)d_in[3];
    const float* Wo = (const float*)d_in[4];
    const float* g1 = (const float*)d_in[5];
    const float* b1 = (const float*)d_in[6];
    const float* g2 = (const float*)d_in[7];
    const float* b2 = (const float*)d_in[8];
    float* out = (float*)d_out;

    cudaFuncSetAttribute(k_prep,  cudaFuncAttributeMaxDynamicSharedMemorySize, KP_SMEM);
    cudaFuncSetAttribute(k_fused, cudaFuncAttributeMaxDynamicSharedMemorySize, KF_SMEM);

    k_prep<<<2, 256, KP_SMEM>>>(Wq, Wk, Wv, Wo);
    k_fused<<<NCHUNK, 256, KF_SMEM>>>(tokens, g1, b1, g2, b2, out);
}

// round 10
// speedup vs baseline: 1.5115x; 1.0320x over previous
#include <cuda_runtime.h>
#include <cuda_bf16.h>
#include <stdint.h>

// ---------------------------------------------------------------------------
// Linear attention (causal QK^T, NO softmax) via chunked prefix-state, with
// projections folded into G = Wq^T Wk / sqrt(H) and W2 = Wo Wv:
//   U = Tn G ; scores = U Tn^T ; Z = tril(scores) Tn + U Tpre ; proj = Z W2^T
// where T_c = Tn_c^T Tn_c, Tpre = exclusive prefix sum of T over chunks.
// m16n128 warp tiles: MMA outputs are re-used as A-fragments of the next MMA
// directly in registers (FlashAttention-style C->A fragment identity), so U
// and Z never touch smem.  Launch 1: k_prep (grid=2).  Launch 2: persistent
// k_fused (grid 256, 2 CTAs/SM) with software grid barriers.
// ---------------------------------------------------------------------------

#define NB      4
#define NSEQ    8192
#define CH      128
#define NCB     (NSEQ / CH)        // 64
#define NCHUNK  (NB * NCB)         // 256
#define TILE    16384              // 128*128
#define RSQRT_H 0.08838834764831845f

__device__ __nv_bfloat16 g_S [NCHUNK * TILE];   // per-chunk gram T_c
__device__ __nv_bfloat16 g_M [NCHUNK * TILE];   // exclusive prefix Tpre
__device__ __nv_bfloat16 g_G [TILE];            // Wq^T Wk / sqrt(H)
__device__ __nv_bfloat16 g_W2[TILE];            // Wo @ Wv

// grid barrier state
__device__ int g_cnt = 0;
__device__ int g_gen = 0;

__device__ __forceinline__ void grid_bar() {
    __syncthreads();
    if (threadIdx.x == 0) {
        __threadfence();
        int gen = *((volatile int*)&g_gen);
        if (atomicAdd(&g_cnt, 1) == NCHUNK - 1) {
            g_cnt = 0;
            __threadfence();
            atomicExch(&g_gen, gen + 1);
        } else {
            while (*((volatile int*)&g_gen) == gen) __nanosleep(32);
        }
        __threadfence();
    }
    __syncthreads();
}

// =========================== helpers =======================================
__device__ __forceinline__ uint32_t smem_u32(const void* p) {
    uint32_t a;
    asm("{ .reg .u64 t; cvta.to.shared.u64 t, %1; cvt.u32.u64 %0, t; }"
        : "=r"(a) : "l"(p));
    return a;
}

__device__ __forceinline__ uint32_t swz(int row, int colg) {
    return (uint32_t)(row * 256) + (uint32_t)(((colg ^ (row & 7)) << 4));
}

__device__ __forceinline__ uint32_t pack_bf16(float lo, float hi) {
    __nv_bfloat162 h;
    h.x = __float2bfloat16(lo);
    h.y = __float2bfloat16(hi);
    return *reinterpret_cast<uint32_t*>(&h);
}

__device__ __forceinline__ void ldm4(uint32_t addr, uint32_t r[4]) {
    asm volatile("ldmatrix.sync.aligned.m8n8.x4.shared.b16 {%0,%1,%2,%3}, [%4];"
                 : "=r"(r[0]), "=r"(r[1]), "=r"(r[2]), "=r"(r[3]) : "r"(addr));
}
__device__ __forceinline__ void ldm4t(uint32_t addr, uint32_t r[4]) {
    asm volatile("ldmatrix.sync.aligned.m8n8.x4.trans.shared.b16 {%0,%1,%2,%3}, [%4];"
                 : "=r"(r[0]), "=r"(r[1]), "=r"(r[2]), "=r"(r[3]) : "r"(addr));
}

__device__ __forceinline__ void mma16816(float* c, const uint32_t a[4],
                                         uint32_t b0, uint32_t b1) {
    asm volatile(
        "mma.sync.aligned.m16n8k16.row.col.f32.bf16.bf16.f32 "
        "{%0,%1,%2,%3},{%4,%5,%6,%7},{%8,%9},{%0,%1,%2,%3};"
        : "+f"(c[0]), "+f"(c[1]), "+f"(c[2]), "+f"(c[3])
        : "r"(a[0]), "r"(a[1]), "r"(a[2]), "r"(a[3]), "r"(b0), "r"(b1));
}

// cp.async 128x128 bf16 gmem tile -> swizzled smem tile
__device__ __forceinline__ void cp_tile(uint32_t dst, const __nv_bfloat16* __restrict__ src,
                                        int tid) {
#pragma unroll
    for (int i = 0; i < 8; i++) {
        int idx = tid + i * 256;
        int row = idx >> 4, g = idx & 15;
        asm volatile("cp.async.cg.shared.global [%0], [%1], 16;"
                     :: "r"(dst + swz(row, g)),
                        "l"((const void*)(((const uint4*)src) + idx)));
    }
}
#define CP_COMMIT() asm volatile("cp.async.commit_group;" ::: "memory")
#define CP_WAIT()   asm volatile("cp.async.wait_all;" ::: "memory")

// fp32 row-major 128x128 gmem -> bf16 swizzled smem tile (256 threads)
__device__ __forceinline__ void load_w(char* dst, const float* __restrict__ W, int tid) {
#pragma unroll
    for (int i = 0; i < 8; i++) {
        int idx = tid + i * 256;
        int row = idx >> 4, g = idx & 15;
        const float4* p = (const float4*)(W + row * 128 + g * 8);
        float4 v0 = p[0], v1 = p[1];
        uint4 o;
        o.x = pack_bf16(v0.x, v0.y);  o.y = pack_bf16(v0.z, v0.w);
        o.z = pack_bf16(v1.x, v1.y);  o.w = pack_bf16(v1.z, v1.w);
        *(uint4*)(dst + swz(row, g)) = o;
    }
}

// ---------------------------------------------------------------------------
// m16 x n128 x k128 MMA, A from smem.  8 warps: warp w owns rows mo=w*16,
// all 128 columns.  acc[16][4] fp32.  ATR/BTR: operand is tile-transposed.
// ---------------------------------------------------------------------------
template <int ATR, int BTR>
__device__ __forceinline__ void mm_s(uint32_t sa, uint32_t sb,
                                     float acc[16][4], int lane, int mo) {
#pragma unroll
    for (int kk = 0; kk < 8; kk++) {
        uint32_t a[4];
        if (!ATR) {
            ldm4(sa + swz(mo + (lane & 15), kk * 2 + (lane >> 4)), a);
        } else {
            ldm4t(sa + swz(kk * 16 + ((lane >> 4) << 3) + (lane & 7),
                           (mo >> 3) + ((lane >> 3) & 1)), a);
        }
#pragma unroll
        for (int nh = 0; nh < 2; nh++) {
            uint32_t b[4][4];
#pragma unroll
            for (int q = 0; q < 4; q++) {
                int idx = nh * 4 + q;
                if (!BTR) {
                    ldm4(sb + swz(idx * 16 + ((lane >> 4) << 3) + (lane & 7),
                                  kk * 2 + ((lane >> 3) & 1)), b[q]);
                } else {
                    ldm4t(sb + swz(kk * 16 + ((lane >> 3) & 1) * 8 + (lane & 7),
                                   idx * 2 + (lane >> 4)), b[q]);
                }
            }
#pragma unroll
            for (int j = 0; j < 8; j++)
                mma16816(acc[nh * 8 + j], a,
                         b[j >> 1][(j & 1) * 2], b[j >> 1][(j & 1) * 2 + 1]);
        }
    }
}

// A from registers (af[8][4] = bf16 A-fragments for k=128), B from smem.
template <int BTR>
__device__ __forceinline__ void mm_f(const uint32_t af[8][4], uint32_t sb,
                                     float acc[16][4], int lane) {
#pragma unroll
    for (int kk = 0; kk < 8; kk++) {
#pragma unroll
        for (int nh = 0; nh < 2; nh++) {
            uint32_t b[4][4];
#pragma unroll
            for (int q = 0; q < 4; q++) {
                int idx = nh * 4 + q;
                if (!BTR) {
                    ldm4(sb + swz(idx * 16 + ((lane >> 4) << 3) + (lane & 7),
                                  kk * 2 + ((lane >> 3) & 1)), b[q]);
                } else {
                    ldm4t(sb + swz(kk * 16 + ((lane >> 3) & 1) * 8 + (lane & 7),
                                   idx * 2 + (lane >> 4)), b[q]);
                }
            }
#pragma unroll
            for (int j = 0; j < 8; j++)
                mma16816(acc[nh * 8 + j], af[kk],
                         b[j >> 1][(j & 1) * 2], b[j >> 1][(j & 1) * 2 + 1]);
        }
    }
}

__device__ __forceinline__ void zacc(float acc[16][4]) {
#pragma unroll
    for (int n = 0; n < 16; n++)
#pragma unroll
        for (int j = 0; j < 4; j++) acc[n][j] = 0.0f;
}

// C-fragments (m16 x n128) -> A-fragments (m16 x k128), in-register, scaled.
// a0=(c0,c1) of n8-tile 2kb; a1=(c2,c3) of 2kb; a2,a3 = same of tile 2kb+1.
__device__ __forceinline__ void cvt_frag(const float acc[16][4], uint32_t af[8][4],
                                         float scale) {
#pragma unroll
    for (int kb = 0; kb < 8; kb++) {
        af[kb][0] = pack_bf16(acc[2 * kb][0] * scale,     acc[2 * kb][1] * scale);
        af[kb][1] = pack_bf16(acc[2 * kb][2] * scale,     acc[2 * kb][3] * scale);
        af[kb][2] = pack_bf16(acc[2 * kb + 1][0] * scale, acc[2 * kb + 1][1] * scale);
        af[kb][3] = pack_bf16(acc[2 * kb + 1][2] * scale, acc[2 * kb + 1][3] * scale);
    }
}

// accum (scaled) -> bf16 row-major gmem tile (m16 layout)
__device__ __forceinline__ void store_bf16(const float acc[16][4],
                                           __nv_bfloat16* __restrict__ dst,
                                           int lane, int mo, float scale) {
    int gq = lane >> 2, t = lane & 3;
#pragma unroll
    for (int nt = 0; nt < 16; nt++) {
        int col = nt * 8 + 2 * t;
        *(uint32_t*)(dst + (mo + gq) * 128 + col) =
            pack_bf16(acc[nt][0] * scale, acc[nt][1] * scale);
        *(uint32_t*)(dst + (mo + 8 + gq) * 128 + col) =
            pack_bf16(acc[nt][2] * scale, acc[nt][3] * scale);
    }
}

// ===========================================================================
// Kernel 0: ONE prep launch (grid=2).  CTA0: G = Wq^T Wk / sqrt(H);
// CTA1: W2 = Wo @ Wv.  fp32 weights read directly.
// ===========================================================================
#define KP_SMEM (2 * 32768)

extern "C" __global__ void __launch_bounds__(256, 1)
k_prep(const float* __restrict__ Wq, const float* __restrict__ Wk,
       const float* __restrict__ Wv, const float* __restrict__ Wo) {
    extern __shared__ char smem[];
    char* a = smem;
    char* b = smem + 32768;
    int tid = threadIdx.x, wid = tid >> 5, lane = tid & 31;
    int mo = wid * 16;
    uint32_t sa = smem_u32(a), sb = smem_u32(b);
    float acc[16][4];

    if (blockIdx.x == 0) {
        load_w(a, Wq, tid);
        load_w(b, Wk, tid);
        __syncthreads();
        zacc(acc);
        mm_s<1, 1>(sa, sb, acc, lane, mo);    // G[t1][t2] = sum_h Wq[h][t1] Wk[h][t2]
        store_bf16(acc, g_G, lane, mo, RSQRT_H);
    } else {
        load_w(a, Wo, tid);
        load_w(b, Wv, tid);
        __syncthreads();
        zacc(acc);
        mm_s<0, 1>(sa, sb, acc, lane, mo);    // W2[o][t] = sum_v Wo[o][v] Wv[v][t]
        store_bf16(acc, g_W2, lane, mo, 1.0f);
    }
}

// ===========================================================================
// Fused persistent kernel. smem: b0=Tn (resident) / b1=G->P / b2=Tpre->W2.
// ===========================================================================
#define KF_SMEM (3 * 32768)

extern "C" __global__ void __launch_bounds__(256, 2)
k_fused(const float* __restrict__ tokens,
        const float* __restrict__ g1, const float* __restrict__ b1v,
        const float* __restrict__ g2, const float* __restrict__ b2v,
        float* __restrict__ out) {
    extern __shared__ char smem[];
    char* b0 = smem;
    char* b1 = smem + 32768;
    char* b2 = smem + 65536;
    int tid = threadIdx.x, wid = tid >> 5, lane = tid & 31;
    int mo = wid * 16;
    int gq = lane >> 2, t = lane & 3;
    int cid = blockIdx.x, base = cid * CH;
    uint32_t sb0 = smem_u32(b0), sb1 = smem_u32(b1), sb2 = smem_u32(b2);

    float acc[16][4];

    // ============================ PHASE A ==================================
    cp_tile(sb1, g_G, tid);                 // G prefetch (used in phase C)
    CP_COMMIT();

    for (int r = wid; r < CH; r += 8) {
        float4 v = ((const float4*)(tokens + (size_t)(base + r) * 128))[lane];
        float s  = v.x + v.y + v.z + v.w;
        float s2 = v.x * v.x + v.y * v.y + v.z * v.z + v.w * v.w;
#pragma unroll
        for (int o = 16; o; o >>= 1) {
            s  += __shfl_xor_sync(0xffffffffu, s, o);
            s2 += __shfl_xor_sync(0xffffffffu, s2, o);
        }
        float mu  = s * (1.0f / 128.0f);
        float var = fmaxf(s2 * (1.0f / 128.0f) - mu * mu, 0.0f);
        float inv = rsqrtf(var + 1e-5f);
        float4 gg = ((const float4*)g1)[lane];
        float4 bb = ((const float4*)b1v)[lane];
        float o0 = (v.x - mu) * inv * gg.x + bb.x;
        float o1 = (v.y - mu) * inv * gg.y + bb.y;
        float o2 = (v.z - mu) * inv * gg.z + bb.z;
        float o3 = (v.w - mu) * inv * gg.w + bb.w;
        uint32_t off = swz(r, lane >> 1) + (lane & 1) * 8;
        *(uint32_t*)(b0 + off)     = pack_bf16(o0, o1);
        *(uint32_t*)(b0 + off + 4) = pack_bf16(o2, o3);
    }
    CP_WAIT();
    __syncthreads();

    // T = Tn^T @ Tn -> g_S
    zacc(acc);
    mm_s<1, 1>(sb0, sb0, acc, lane, mo);
    store_bf16(acc, g_S + (size_t)cid * TILE, lane, mo, 1.0f);

    grid_bar();                             // all T visible

    // ============================ PHASE B ==================================
    {
        int tg = cid * 256 + tid;
        int b = tg >> 14, e = tg & 16383;
        const __nv_bfloat16* S = g_S + (size_t)b * NCB * TILE + e;
        __nv_bfloat16* M = g_M + (size_t)b * NCB * TILE + e;
        float s = 0.0f;
#pragma unroll 8
        for (int c = 0; c < NCB; c++) {
            M[(size_t)c * TILE] = __float2bfloat16(s);
            s += __bfloat162float(S[(size_t)c * TILE]);
        }
    }

    grid_bar();                             // all Tpre visible

    // ============================ PHASE C ==================================
    // Tpre -> b2 overlapped with U = Tn @ G  (B = G trans)
    cp_tile(sb2, g_M + (size_t)cid * TILE, tid);
    CP_COMMIT();
    zacc(acc);
    mm_s<0, 1>(sb0, sb1, acc, lane, mo);    // U[i][t2]

    uint32_t Uf[8][4];
    cvt_frag(acc, Uf, 1.0f);                // U stays in registers

    CP_WAIT();
    __syncthreads();                        // S1: G dead, Tpre visible

    // scores = U @ Tn^T  (A from regs, B = Tn non-trans)
    zacc(acc);
    mm_f<0>(Uf, sb0, acc, lane);

    // masked P -> b1 (overwrites G)
#pragma unroll
    for (int nt = 0; nt < 16; nt++) {
        int col = nt * 8 + 2 * t;
        int r0 = mo + gq, r1 = r0 + 8;
        float v0 = (col     <= r0) ? acc[nt][0] : 0.0f;
        float v1 = (col + 1 <= r0) ? acc[nt][1] : 0.0f;
        float v2 = (col     <= r1) ? acc[nt][2] : 0.0f;
        float v3 = (col + 1 <= r1) ? acc[nt][3] : 0.0f;
        *(uint32_t*)(b1 + swz(r0, nt) + (col & 7) * 2) = pack_bf16(v0, v1);
        *(uint32_t*)(b1 + swz(r1, nt) + (col & 7) * 2) = pack_bf16(v2, v3);
    }

    // Z = U @ Tpre  (A from regs, B = Tpre trans) -- overlaps the P store
    zacc(acc);
    mm_f<1>(Uf, sb2, acc, lane);
    __syncthreads();                        // S2: P visible, Tpre reads done

    // W2 -> b2 (overwrites Tpre), overlapped with Z += P @ Tn
    cp_tile(sb2, g_W2, tid);
    CP_COMMIT();
    mm_s<0, 1>(sb1, sb0, acc, lane, mo);    // A = P (smem), B = Tn trans

    uint32_t Zf[8][4];
    cvt_frag(acc, Zf, RSQRT_H);             // Z stays in registers

    CP_WAIT();
    __syncthreads();                        // S3: W2 visible, P dead

    // proj = Z @ W2^T  (A from regs, B = W2 non-trans)
    zacc(acc);
    mm_f<0>(Zf, sb2, acc, lane);
    __syncthreads();                        // S4: Tn (b0) dead everywhere

    // 0.1*proj -> b0 bf16 row-major
#pragma unroll
    for (int nt = 0; nt < 16; nt++) {
        int col = nt * 8 + 2 * t;
        int r0 = mo + gq, r1 = r0 + 8;
        *(uint32_t*)(b0 + (r0 * 128 + col) * 2) =
            pack_bf16(0.1f * acc[nt][0], 0.1f * acc[nt][1]);
        *(uint32_t*)(b0 + (r1 * 128 + col) * 2) =
            pack_bf16(0.1f * acc[nt][2], 0.1f * acc[nt][3]);
    }
    __syncthreads();

    // LN2(tokens + res) -> out
    for (int r = wid; r < CH; r += 8) {
        float4 tv = ((const float4*)(tokens + (size_t)(base + r) * 128))[lane];
        uint2 pr = *(const uint2*)(b0 + (r * 128 + lane * 4) * 2);
        __nv_bfloat162 p0 = *reinterpret_cast<__nv_bfloat162*>(&pr.x);
        __nv_bfloat162 p1 = *reinterpret_cast<__nv_bfloat162*>(&pr.y);
        float x0 = tv.x + __bfloat162float(p0.x);
        float x1 = tv.y + __bfloat162float(p0.y);
        float x2 = tv.z + __bfloat162float(p1.x);
        float x3 = tv.w + __bfloat162float(p1.y);
        float s  = x0 + x1 + x2 + x3;
        float s2 = x0 * x0 + x1 * x1 + x2 * x2 + x3 * x3;
#pragma unroll
        for (int o = 16; o; o >>= 1) {
            s  += __shfl_xor_sync(0xffffffffu, s, o);
            s2 += __shfl_xor_sync(0xffffffffu, s2, o);
        }
        float mu  = s * (1.0f / 128.0f);
        float var = fmaxf(s2 * (1.0f / 128.0f) - mu * mu, 0.0f);
        float inv = rsqrtf(var + 1e-5f);
        float4 gg = ((const float4*)g2)[lane];
        float4 bb = ((const float4*)b2v)[lane];
        float4 o4;
        o4.x = (x0 - mu) * inv * gg.x + bb.x;
        o4.y = (x1 - mu) * inv * gg.y + bb.y;
        o4.z = (x2 - mu) * inv * gg.z + bb.z;
        o4.w = (x3 - mu) * inv * gg.w + bb.w;
        ((float4*)(out + (size_t)(base + r) * 128))[lane] = o4;
    }
}

// ===========================================================================
extern "C" void kernel_launch(void* const* d_in, const int* in_sizes, int n_in,
                              void* d_out, int out_size) {
    const float* tokens = (const float*)d_in[0];
    const float* Wq = (const float*)d_in[1];
    const float* Wk = (const float*)d_in[2];
    const float* Wv = (const float*)d_in[3];
    const float* Wo = (const float*)d_in[4];
    const float* g1 = (const float*)d_in[5];
    const float* b1 = (const float*)d_in[6];
    const float* g2 = (const float*)d_in[7];
    const float* b2 = (const float*)d_in[8];
    float* out = (float*)d_out;

    cudaFuncSetAttribute(k_prep,  cudaFuncAttributeMaxDynamicSharedMemorySize, KP_SMEM);
    cudaFuncSetAttribute(k_fused, cudaFuncAttributeMaxDynamicSharedMemorySize, KF_SMEM);

    k_prep<<<2, 256, KP_SMEM>>>(Wq, Wk, Wv, Wo);
    k_fused<<<NCHUNK, 256, KF_SMEM>>>(tokens, g1, b1, g2, b2, out);
}

// round 11
// speedup vs baseline: 1.5123x; 1.0005x over previous
#include <cuda_runtime.h>
#include <cuda_fp16.h>
#include <stdint.h>

// ---------------------------------------------------------------------------
// Linear attention (causal QK^T, NO softmax) via chunked prefix-state, with
// projections folded into G' = (Wq^T Wk / sqrt(H)) * 1024 and W2 = Wo Wv:
//   U' = Tn G' ; scores' = U' Tn^T ; Z' = tril(scores') Tn + U' Tpre
//   out = LN2(x + (0.1/1024) * Z' W2^T)
// where T_c = Tn_c^T Tn_c, Tpre = exclusive prefix sum of T over chunks.
// ALL tensors fp16; phase-C MMAs use f16 accumulators (2 regs/tile), enabling
// a fused dual-MMA (scores' and Z' together, 32 indep chains) and direct
// C-frag -> A-frag reuse (f16 identity).  Launch 1: k_prep (grid=2).
// Launch 2: persistent k_fused (grid 256, 2 CTAs/SM) + software grid barriers.
// ---------------------------------------------------------------------------

#define NB      4
#define NSEQ    8192
#define CH      128
#define NCB     (NSEQ / CH)        // 64
#define NCHUNK  (NB * NCB)         // 256
#define TILE    16384              // 128*128
#define RSQRT_H 0.08838834764831845f
#define PRESCALE 1024.0f
#define FINAL_SCALE (0.1f / 1024.0f)

__device__ __half g_S [NCHUNK * TILE];   // per-chunk gram T_c
__device__ __half g_M [NCHUNK * TILE];   // exclusive prefix Tpre
__device__ __half g_G [TILE];            // (Wq^T Wk / sqrt(H)) * 1024
__device__ __half g_W2[TILE];            // Wo @ Wv

// grid barrier state
__device__ int g_cnt = 0;
__device__ int g_gen = 0;

__device__ __forceinline__ void grid_bar() {
    __syncthreads();
    if (threadIdx.x == 0) {
        __threadfence();
        int gen = *((volatile int*)&g_gen);
        if (atomicAdd(&g_cnt, 1) == NCHUNK - 1) {
            g_cnt = 0;
            __threadfence();
            atomicExch(&g_gen, gen + 1);
        } else {
            while (*((volatile int*)&g_gen) == gen) __nanosleep(32);
        }
        __threadfence();
    }
    __syncthreads();
}

// =========================== helpers =======================================
__device__ __forceinline__ uint32_t smem_u32(const void* p) {
    uint32_t a;
    asm("{ .reg .u64 t; cvta.to.shared.u64 t, %1; cvt.u32.u64 %0, t; }"
        : "=r"(a) : "l"(p));
    return a;
}

__device__ __forceinline__ uint32_t swz(int row, int colg) {
    return (uint32_t)(row * 256) + (uint32_t)(((colg ^ (row & 7)) << 4));
}

__device__ __forceinline__ uint32_t pack_h(float lo, float hi) {
    __half2 h = __floats2half2_rn(lo, hi);
    return *reinterpret_cast<uint32_t*>(&h);
}

__device__ __forceinline__ void ldm4(uint32_t addr, uint32_t r[4]) {
    asm volatile("ldmatrix.sync.aligned.m8n8.x4.shared.b16 {%0,%1,%2,%3}, [%4];"
                 : "=r"(r[0]), "=r"(r[1]), "=r"(r[2]), "=r"(r[3]) : "r"(addr));
}
__device__ __forceinline__ void ldm4t(uint32_t addr, uint32_t r[4]) {
    asm volatile("ldmatrix.sync.aligned.m8n8.x4.trans.shared.b16 {%0,%1,%2,%3}, [%4];"
                 : "=r"(r[0]), "=r"(r[1]), "=r"(r[2]), "=r"(r[3]) : "r"(addr));
}

// f16 inputs, f32 accum
__device__ __forceinline__ void mma_hf(float* c, const uint32_t a[4],
                                       uint32_t b0, uint32_t b1) {
    asm volatile(
        "mma.sync.aligned.m16n8k16.row.col.f32.f16.f16.f32 "
        "{%0,%1,%2,%3},{%4,%5,%6,%7},{%8,%9},{%0,%1,%2,%3};"
        : "+f"(c[0]), "+f"(c[1]), "+f"(c[2]), "+f"(c[3])
        : "r"(a[0]), "r"(a[1]), "r"(a[2]), "r"(a[3]), "r"(b0), "r"(b1));
}
// f16 inputs, f16 accum (2 regs)
__device__ __forceinline__ void mma_hh(uint32_t c[2], const uint32_t a[4],
                                       uint32_t b0, uint32_t b1) {
    asm volatile(
        "mma.sync.aligned.m16n8k16.row.col.f16.f16.f16.f16 "
        "{%0,%1},{%2,%3,%4,%5},{%6,%7},{%0,%1};"
        : "+r"(c[0]), "+r"(c[1])
        : "r"(a[0]), "r"(a[1]), "r"(a[2]), "r"(a[3]), "r"(b0), "r"(b1));
}

// cp.async 128x128 f16 gmem tile -> swizzled smem tile
__device__ __forceinline__ void cp_tile(uint32_t dst, const __half* __restrict__ src,
                                        int tid) {
#pragma unroll
    for (int i = 0; i < 8; i++) {
        int idx = tid + i * 256;
        int row = idx >> 4, g = idx & 15;
        asm volatile("cp.async.cg.shared.global [%0], [%1], 16;"
                     :: "r"(dst + swz(row, g)),
                        "l"((const void*)(((const uint4*)src) + idx)));
    }
}
#define CP_COMMIT() asm volatile("cp.async.commit_group;" ::: "memory")
#define CP_WAIT()   asm volatile("cp.async.wait_all;" ::: "memory")

// fp32 row-major 128x128 gmem -> f16 swizzled smem tile (256 threads)
__device__ __forceinline__ void load_w(char* dst, const float* __restrict__ W, int tid) {
#pragma unroll
    for (int i = 0; i < 8; i++) {
        int idx = tid + i * 256;
        int row = idx >> 4, g = idx & 15;
        const float4* p = (const float4*)(W + row * 128 + g * 8);
        float4 v0 = p[0], v1 = p[1];
        uint4 o;
        o.x = pack_h(v0.x, v0.y);  o.y = pack_h(v0.z, v0.w);
        o.z = pack_h(v1.x, v1.y);  o.w = pack_h(v1.z, v1.w);
        *(uint4*)(dst + swz(row, g)) = o;
    }
}

// B-operand ldmatrix for n-half nh (8 n8-tiles), k-block kk.
template <int BTR>
__device__ __forceinline__ void ldB(uint32_t sb, int kk, int nh, int lane,
                                    uint32_t b[4][4]) {
#pragma unroll
    for (int q = 0; q < 4; q++) {
        int idx = nh * 4 + q;
        if (!BTR) {
            ldm4(sb + swz(idx * 16 + ((lane >> 4) << 3) + (lane & 7),
                          kk * 2 + ((lane >> 3) & 1)), b[q]);
        } else {
            ldm4t(sb + swz(kk * 16 + ((lane >> 3) & 1) * 8 + (lane & 7),
                           idx * 2 + (lane >> 4)), b[q]);
        }
    }
}

// m16 x n128 x k128, A from smem, f32 accum.
template <int ATR, int BTR>
__device__ __forceinline__ void mm_s32(uint32_t sa, uint32_t sb,
                                       float acc[16][4], int lane, int mo) {
#pragma unroll
    for (int kk = 0; kk < 8; kk++) {
        uint32_t a[4];
        if (!ATR) {
            ldm4(sa + swz(mo + (lane & 15), kk * 2 + (lane >> 4)), a);
        } else {
            ldm4t(sa + swz(kk * 16 + ((lane >> 4) << 3) + (lane & 7),
                           (mo >> 3) + ((lane >> 3) & 1)), a);
        }
#pragma unroll
        for (int nh = 0; nh < 2; nh++) {
            uint32_t b[4][4];
            ldB<BTR>(sb, kk, nh, lane, b);
#pragma unroll
            for (int j = 0; j < 8; j++)
                mma_hf(acc[nh * 8 + j], a,
                       b[j >> 1][(j & 1) * 2], b[j >> 1][(j & 1) * 2 + 1]);
        }
    }
}

// m16 x n128 x k128, A from smem (non-trans), f16 accum.
template <int BTR>
__device__ __forceinline__ void mm_s16(uint32_t sa, uint32_t sb,
                                       uint32_t acc[16][2], int lane, int mo) {
#pragma unroll
    for (int kk = 0; kk < 8; kk++) {
        uint32_t a[4];
        ldm4(sa + swz(mo + (lane & 15), kk * 2 + (lane >> 4)), a);
#pragma unroll
        for (int nh = 0; nh < 2; nh++) {
            uint32_t b[4][4];
            ldB<BTR>(sb, kk, nh, lane, b);
#pragma unroll
            for (int j = 0; j < 8; j++)
                mma_hh(acc[nh * 8 + j], a,
                       b[j >> 1][(j & 1) * 2], b[j >> 1][(j & 1) * 2 + 1]);
        }
    }
}

// Fused dual MMA: A = f16 C-frags (identity), two B tiles (both non-trans),
// two f16 accumulators.  32 independent accumulate chains.
__device__ __forceinline__ void mm_dual(const uint32_t U[16][2],
                                        uint32_t sbA, uint32_t sbB,
                                        uint32_t accA[16][2], uint32_t accB[16][2],
                                        int lane) {
#pragma unroll
    for (int kk = 0; kk < 8; kk++) {
        uint32_t a[4] = {U[2 * kk][0], U[2 * kk][1], U[2 * kk + 1][0], U[2 * kk + 1][1]};
        {
            uint32_t b[4][4];
#pragma unroll
            for (int nh = 0; nh < 2; nh++) {
                ldB<0>(sbA, kk, nh, lane, b);
#pragma unroll
                for (int j = 0; j < 8; j++)
                    mma_hh(accA[nh * 8 + j], a,
                           b[j >> 1][(j & 1) * 2], b[j >> 1][(j & 1) * 2 + 1]);
            }
        }
        {
            uint32_t b[4][4];
#pragma unroll
            for (int nh = 0; nh < 2; nh++) {
                ldB<0>(sbB, kk, nh, lane, b);
#pragma unroll
                for (int j = 0; j < 8; j++)
                    mma_hh(accB[nh * 8 + j], a,
                           b[j >> 1][(j & 1) * 2], b[j >> 1][(j & 1) * 2 + 1]);
            }
        }
    }
}

// proj: A = f16 C-frags, B non-trans, f32 accum.
__device__ __forceinline__ void mm_fp(const uint32_t Z[16][2], uint32_t sb,
                                      float acc[16][4], int lane) {
#pragma unroll
    for (int kk = 0; kk < 8; kk++) {
        uint32_t a[4] = {Z[2 * kk][0], Z[2 * kk][1], Z[2 * kk + 1][0], Z[2 * kk + 1][1]};
#pragma unroll
        for (int nh = 0; nh < 2; nh++) {
            uint32_t b[4][4];
            ldB<0>(sb, kk, nh, lane, b);
#pragma unroll
            for (int j = 0; j < 8; j++)
                mma_hf(acc[nh * 8 + j], a,
                       b[j >> 1][(j & 1) * 2], b[j >> 1][(j & 1) * 2 + 1]);
        }
    }
}

__device__ __forceinline__ void zacc(float acc[16][4]) {
#pragma unroll
    for (int n = 0; n < 16; n++)
#pragma unroll
        for (int j = 0; j < 4; j++) acc[n][j] = 0.0f;
}
__device__ __forceinline__ void zacc16(uint32_t acc[16][2]) {
#pragma unroll
    for (int n = 0; n < 16; n++) { acc[n][0] = 0u; acc[n][1] = 0u; }
}

// f32 accum (scaled) -> f16 row-major gmem tile (m16 layout)
__device__ __forceinline__ void store_f16(const float acc[16][4],
                                          __half* __restrict__ dst,
                                          int lane, int mo, float scale) {
    int gq = lane >> 2, t = lane & 3;
#pragma unroll
    for (int nt = 0; nt < 16; nt++) {
        int col = nt * 8 + 2 * t;
        *(uint32_t*)(dst + (mo + gq) * 128 + col) =
            pack_h(acc[nt][0] * scale, acc[nt][1] * scale);
        *(uint32_t*)(dst + (mo + 8 + gq) * 128 + col) =
            pack_h(acc[nt][2] * scale, acc[nt][3] * scale);
    }
}

// ===========================================================================
// Kernel 0: ONE prep launch (grid=2).
//   CTA0: G' = (Wq^T Wk / sqrt(H)) * 1024     CTA1: W2 = Wo @ Wv
// ===========================================================================
#define KP_SMEM (2 * 32768)

extern "C" __global__ void __launch_bounds__(256, 1)
k_prep(const float* __restrict__ Wq, const float* __restrict__ Wk,
       const float* __restrict__ Wv, const float* __restrict__ Wo) {
    extern __shared__ char smem[];
    char* a = smem;
    char* b = smem + 32768;
    int tid = threadIdx.x, wid = tid >> 5, lane = tid & 31;
    int mo = wid * 16;
    uint32_t sa = smem_u32(a), sb = smem_u32(b);
    float acc[16][4];

    if (blockIdx.x == 0) {
        load_w(a, Wq, tid);
        load_w(b, Wk, tid);
        __syncthreads();
        zacc(acc);
        mm_s32<1, 1>(sa, sb, acc, lane, mo);    // G[t1][t2] = sum_h Wq[h][t1] Wk[h][t2]
        store_f16(acc, g_G, lane, mo, RSQRT_H * PRESCALE);
    } else {
        load_w(a, Wo, tid);
        load_w(b, Wv, tid);
        __syncthreads();
        zacc(acc);
        mm_s32<0, 1>(sa, sb, acc, lane, mo);    // W2[o][t] = sum_v Wo[o][v] Wv[v][t]
        store_f16(acc, g_W2, lane, mo, 1.0f);
    }
}

// ===========================================================================
// Fused persistent kernel. smem: b0=Tn (resident) -> proj / b1=G->P / b2=Tpre->W2.
// ===========================================================================
#define KF_SMEM (3 * 32768)

extern "C" __global__ void __launch_bounds__(256, 2)
k_fused(const float* __restrict__ tokens,
        const float* __restrict__ g1, const float* __restrict__ b1v,
        const float* __restrict__ g2, const float* __restrict__ b2v,
        float* __restrict__ out) {
    extern __shared__ char smem[];
    char* b0 = smem;
    char* b1 = smem + 32768;
    char* b2 = smem + 65536;
    int tid = threadIdx.x, wid = tid >> 5, lane = tid & 31;
    int mo = wid * 16;
    int gq = lane >> 2, t = lane & 3;
    int cid = blockIdx.x, base = cid * CH;
    uint32_t sb0 = smem_u32(b0), sb1 = smem_u32(b1), sb2 = smem_u32(b2);

    // ============================ PHASE A ==================================
    cp_tile(sb1, g_G, tid);                 // G prefetch (used in phase C)
    CP_COMMIT();

    for (int r = wid; r < CH; r += 8) {
        float4 v = ((const float4*)(tokens + (size_t)(base + r) * 128))[lane];
        float s  = v.x + v.y + v.z + v.w;
        float s2 = v.x * v.x + v.y * v.y + v.z * v.z + v.w * v.w;
#pragma unroll
        for (int o = 16; o; o >>= 1) {
            s  += __shfl_xor_sync(0xffffffffu, s, o);
            s2 += __shfl_xor_sync(0xffffffffu, s2, o);
        }
        float mu  = s * (1.0f / 128.0f);
        float var = fmaxf(s2 * (1.0f / 128.0f) - mu * mu, 0.0f);
        float inv = rsqrtf(var + 1e-5f);
        float4 gg = ((const float4*)g1)[lane];
        float4 bb = ((const float4*)b1v)[lane];
        float o0 = (v.x - mu) * inv * gg.x + bb.x;
        float o1 = (v.y - mu) * inv * gg.y + bb.y;
        float o2 = (v.z - mu) * inv * gg.z + bb.z;
        float o3 = (v.w - mu) * inv * gg.w + bb.w;
        uint32_t off = swz(r, lane >> 1) + (lane & 1) * 8;
        *(uint32_t*)(b0 + off)     = pack_h(o0, o1);
        *(uint32_t*)(b0 + off + 4) = pack_h(o2, o3);
    }
    CP_WAIT();
    __syncthreads();

    // T = Tn^T @ Tn -> g_S  (f32 accum)
    {
        float acc[16][4];
        zacc(acc);
        mm_s32<1, 1>(sb0, sb0, acc, lane, mo);
        store_f16(acc, g_S + (size_t)cid * TILE, lane, mo, 1.0f);
    }

    grid_bar();                             // all T visible

    // ============================ PHASE B ==================================
    {
        int tg = cid * 256 + tid;
        int b = tg >> 14, e = tg & 16383;
        const __half* S = g_S + (size_t)b * NCB * TILE + e;
        __half* M = g_M + (size_t)b * NCB * TILE + e;
        float s = 0.0f;
#pragma unroll 8
        for (int c = 0; c < NCB; c++) {
            M[(size_t)c * TILE] = __float2half(s);
            s += __half2float(S[(size_t)c * TILE]);
        }
    }

    grid_bar();                             // all Tpre visible

    // ============================ PHASE C ==================================
    // Tpre -> b2 overlapped with U' = Tn @ G'  (f16 acc; B = G trans)
    cp_tile(sb2, g_M + (size_t)cid * TILE, tid);
    CP_COMMIT();

    uint32_t Ua[16][2];
    zacc16(Ua);
    mm_s16<1>(sb0, sb1, Ua, lane, mo);      // U'[i][t2]

    CP_WAIT();
    __syncthreads();                        // S1: G dead, Tpre visible

    // fused: scores' = U' Tn^T  and  Z' = U' Tpre  (Tpre symmetric -> non-trans)
    uint32_t accS[16][2], accZ[16][2];
    zacc16(accS);
    zacc16(accZ);
    mm_dual(Ua, sb0, sb2, accS, accZ, lane);
    __syncthreads();                        // S2: Tpre dead everywhere

    cp_tile(sb2, g_W2, tid);                // W2 -> b2 under the P store + Z mma
    CP_COMMIT();

    // masked P -> b1 (own rows only; warp-local)
    {
        __half z = __float2half(0.0f);
#pragma unroll
        for (int nt = 0; nt < 16; nt++) {
            int col = nt * 8 + 2 * t;
            int r0 = mo + gq, r1 = r0 + 8;
            __half2 h0 = *reinterpret_cast<__half2*>(&accS[nt][0]);
            __half2 h1 = *reinterpret_cast<__half2*>(&accS[nt][1]);
            if (col     > r0) h0.x = z;
            if (col + 1 > r0) h0.y = z;
            if (col     > r1) h1.x = z;
            if (col + 1 > r1) h1.y = z;
            *(uint32_t*)(b1 + swz(r0, nt) + (col & 7) * 2) = *reinterpret_cast<uint32_t*>(&h0);
            *(uint32_t*)(b1 + swz(r1, nt) + (col & 7) * 2) = *reinterpret_cast<uint32_t*>(&h1);
        }
    }
    __syncwarp();                           // P rows (own) visible to own warp

    // Z' += P' @ Tn  (A = P own rows, B = Tn trans)
    mm_s16<1>(sb1, sb0, accZ, lane, mo);

    CP_WAIT();
    __syncthreads();                        // S3: W2 ready; Tn, P dead everywhere

    // proj' = Z' @ W2^T  (f32 accum; A = accZ frags directly)
    float accP[16][4];
    zacc(accP);
    mm_fp(accZ, sb2, accP, lane);

    // proj' -> b0 f16 row-major (raw; final scale applied at LN2 read)
#pragma unroll
    for (int nt = 0; nt < 16; nt++) {
        int col = nt * 8 + 2 * t;
        int r0 = mo + gq, r1 = r0 + 8;
        *(uint32_t*)(b0 + (r0 * 128 + col) * 2) = pack_h(accP[nt][0], accP[nt][1]);
        *(uint32_t*)(b0 + (r1 * 128 + col) * 2) = pack_h(accP[nt][2], accP[nt][3]);
    }
    __syncthreads();                        // S4: proj visible

    // LN2(tokens + FINAL_SCALE * proj') -> out
    for (int r = wid; r < CH; r += 8) {
        float4 tv = ((const float4*)(tokens + (size_t)(base + r) * 128))[lane];
        uint2 pr = *(const uint2*)(b0 + (r * 128 + lane * 4) * 2);
        __half2 p0 = *reinterpret_cast<__half2*>(&pr.x);
        __half2 p1 = *reinterpret_cast<__half2*>(&pr.y);
        float x0 = tv.x + FINAL_SCALE * __half2float(p0.x);
        float x1 = tv.y + FINAL_SCALE * __half2float(p0.y);
        float x2 = tv.z + FINAL_SCALE * __half2float(p1.x);
        float x3 = tv.w + FINAL_SCALE * __half2float(p1.y);
        float s  = x0 + x1 + x2 + x3;
        float s2 = x0 * x0 + x1 * x1 + x2 * x2 + x3 * x3;
#pragma unroll
        for (int o = 16; o; o >>= 1) {
            s  += __shfl_xor_sync(0xffffffffu, s, o);
            s2 += __shfl_xor_sync(0xffffffffu, s2, o);
        }
        float mu  = s * (1.0f / 128.0f);
        float var = fmaxf(s2 * (1.0f / 128.0f) - mu * mu, 0.0f);
        float inv = rsqrtf(var + 1e-5f);
        float4 gg = ((const float4*)g2)[lane];
        float4 bb = ((const float4*)b2v)[lane];
        float4 o4;
        o4.x = (x0 - mu) * inv * gg.x + bb.x;
        o4.y = (x1 - mu) * inv * gg.y + bb.y;
        o4.z = (x2 - mu) * inv * gg.z + bb.z;
        o4.w = (x3 - mu) * inv * gg.w + bb.w;
        ((float4*)(out + (size_t)(base + r) * 128))[lane] = o4;
    }
}

// ===========================================================================
extern "C" void kernel_launch(void* const* d_in, const int* in_sizes, int n_in,
                              void* d_out, int out_size) {
    const float* tokens = (const float*)d_in[0];
    const float* Wq = (const float*)d_in[1];
    const float* Wk = (const float*)d_in[2];
    const float* Wv = (const float*)d_in[3];
    const float* Wo = (const float*)d_in[4];
    const float* g1 = (const float*)d_in[5];
    const float* b1 = (const float*)d_in[6];
    const float* g2 = (const float*)d_in[7];
    const float* b2 = (const float*)d_in[8];
    float* out = (float*)d_out;

    cudaFuncSetAttribute(k_prep,  cudaFuncAttributeMaxDynamicSharedMemorySize, KP_SMEM);
    cudaFuncSetAttribute(k_fused, cudaFuncAttributeMaxDynamicSharedMemorySize, KF_SMEM);

    k_prep<<<2, 256, KP_SMEM>>>(Wq, Wk, Wv, Wo);
    k_fused<<<NCHUNK, 256, KF_SMEM>>>(tokens, g1, b1, g2, b2, out);
}